// round 12
// baseline (speedup 1.0000x reference)
#include <cuda_runtime.h>
#include <cuda_fp16.h>
#include <cstdint>

#define DD 64
#define LL 128
#define KROWS 8192
#define MROWS 64
#define NBLK (KROWS/MROWS)   // 128 CTAs
#define NTHR 128
#define XSTR 132

typedef unsigned int u32;

// smem byte offsets
#define SM_B   0          // W fp16: 256 rows x 128B (32KB); later sWa/sWf
#define SM_X   32768      // x: 64 x 132 floats = 33792B; later sHfin/sCst
#define SM_CA  66560      // 256 floats
#define SM_CB  67584      // 256 floats
#define SM_RED 68608      // 128 floats
#define SM_FIN 69120      // 3*64 floats
#define SM_FLG 69888      // 4B
#define SM_TOT 69952

__device__ float g_acc[128];
__device__ unsigned int g_ctr = 0;

__device__ __forceinline__ float fexp(float x){
    x = fmaxf(fminf(x, 30.f), -30.f);
    return __expf(x);
}
__device__ __forceinline__ float sigf(float x){
    return __fdividef(1.0f, 1.0f + fexp(-x));
}
__device__ __forceinline__ float tanhp(float x){
    return 2.0f * __fdividef(1.0f, 1.0f + fexp(-2.0f*x)) - 1.0f;
}
__device__ __forceinline__ float tanha(float x){
    float r; asm("tanh.approx.f32 %0, %1;" : "=f"(r) : "f"(x)); return r;
}
__device__ __forceinline__ float siga(float x){
    return fmaf(0.5f, tanha(0.5f*x), 0.5f);
}
__device__ __forceinline__ u32 smem_u32(const void* p){
    u32 a;
    asm("{ .reg .u64 t; cvta.to.shared.u64 t, %1; cvt.u32.u64 %0, t; }" : "=r"(a) : "l"(p));
    return a;
}

__device__ __forceinline__ void mma_fp16(float* c, const u32* a, const u32* b){
    asm volatile("mma.sync.aligned.m16n8k16.row.col.f32.f16.f16.f32 "
        "{%0,%1,%2,%3}, {%4,%5,%6,%7}, {%8,%9}, {%0,%1,%2,%3};\n"
        : "+f"(c[0]),"+f"(c[1]),"+f"(c[2]),"+f"(c[3])
        : "r"(a[0]),"r"(a[1]),"r"(a[2]),"r"(a[3]), "r"(b[0]),"r"(b[1]));
}

#define LDSM4(r0,r1,r2,r3, a) asm volatile( \
    "ldmatrix.sync.aligned.m8n8.x4.shared.b16 {%0,%1,%2,%3}, [%4];" \
    : "=r"(r0),"=r"(r1),"=r"(r2),"=r"(r3) : "r"(a))

// ---------- single fused kernel: warp-autonomous recurrence ----------
__global__ void __launch_bounds__(NTHR,1)
lstm_kernel(const float* __restrict__ x,
            const float* __restrict__ W_num,  const float* __restrict__ b_num,
            const float* __restrict__ W_ih,   const float* __restrict__ W_hh,
            const float* __restrict__ b_ih,   const float* __restrict__ b_hh,
            const float* __restrict__ W_aout, const float* __restrict__ b_aout,
            const float* __restrict__ W_fh,   const float* __restrict__ b_fh,
            const float* __restrict__ W_iouh, const float* __restrict__ b_iouh,
            const float* __restrict__ W_oout, const float* __restrict__ b_oout,
            float* __restrict__ out){
    extern __shared__ char sm[];
    const int tid  = threadIdx.x;
    const int wid  = tid >> 5;
    const int lane = tid & 31;
    const int g    = lane >> 2;      // 0..7
    const int tq   = lane & 3;       // 0..3
    const int wrow = wid * 16;       // this warp's row base
    const int r0   = blockIdx.x * MROWS;

    float* sXf = (float*)(sm + SM_X);
    float* sCa = (float*)(sm + SM_CA);
    float* sCb = (float*)(sm + SM_CB);
    float* sRd = (float*)(sm + SM_RED);

    // ---- prep: consts + fp16 W (row n == W row; swizzle on n&7) ----
    for (int n = tid; n < 256; n += NTHR){
        float sa = 0.f, sc = 0.f;
        #pragma unroll 8
        for (int k = 0; k < DD; k++){
            float w = __ldg(W_ih + n*(2*DD) + k);
            sa += w * __ldg(W_num + k);
            sc += w * __ldg(b_num + k);
        }
        sCa[n] = sa;
        sCb[n] = sc + __ldg(b_ih + n) + __ldg(b_hh + n);
        #pragma unroll 8
        for (int k = 0; k < DD; k += 2){
            __half h0 = __float2half_rn(__ldg(W_hh + n*DD + k));
            __half h1 = __float2half_rn(__ldg(W_hh + n*DD + k + 1));
            u32 hp = (u32)__half_as_ushort(h0) | ((u32)__half_as_ushort(h1) << 16);
            u32 off = (u32)n*128 + (u32)k*2;
            u32 sw  = off ^ (((u32)n & 7u) << 4);
            *(u32*)(sm + SM_B + sw) = hp;
        }
    }
    for (int idx = tid*4; idx < MROWS*LL; idx += NTHR*4){
        int rr = idx >> 7, tt = idx & 127;
        float4 v = *(const float4*)(x + (size_t)(r0 + rr)*LL + tt);
        *(float4*)(sXf + rr*XSTR + tt) = v;
    }
    sRd[tid] = 0.f;
    __syncthreads();

    // ldmatrix per-lane address offsets (two x4 per tile: k 0..31, k 32..63)
    const int row8 = lane & 7, mi = lane >> 3;
    const u32 Bs = smem_u32(sm + SM_B);
    const u32 offq0 = (u32)(row8*128) + (((u32)(mi*16))      ^ ((u32)row8 << 4));
    const u32 offq1 = (u32)(row8*128) + (((u32)(64 + mi*16)) ^ ((u32)row8 << 4));

    u32 Areg[4][4], Anext[2][4];
    #pragma unroll
    for (int K = 0; K < 4; K++)
        #pragma unroll
        for (int q = 0; q < 4; q++) Areg[K][q] = 0u;
    float creg[32];
    #pragma unroll
    for (int i = 0; i < 32; i++) creg[i] = 0.f;

    for (int t = 0; t < LL; t++){
        float xv[2];
        xv[0] = sXf[(wrow + g    )*XSTR + t];
        xv[1] = sXf[(wrow + g + 8)*XSTR + t];

        #pragma unroll
        for (int dh = 0; dh < 2; dh++){
            float acc[64];
            #pragma unroll
            for (int i = 0; i < 64; i++) acc[i] = 0.f;

            #pragma unroll
            for (int G = 0; G < 4; G++){
                #pragma unroll
                for (int jjl = 0; jjl < 4; jjl++){
                    int j = G*8 + dh*4 + jjl;
                    u32 b0,b1,b2,b3,b4,b5,b6,b7;
                    LDSM4(b0,b1,b2,b3, Bs + (u32)j*1024 + offq0);
                    LDSM4(b4,b5,b6,b7, Bs + (u32)j*1024 + offq1);
                    float* a4 = acc + (G*4 + jjl)*4;
                    u32 p0[2] = {b0,b1}, p1[2] = {b2,b3}, p2[2] = {b4,b5}, p3[2] = {b6,b7};
                    mma_fp16(a4, Areg[0], p0);
                    mma_fp16(a4, Areg[1], p1);
                    mma_fp16(a4, Areg[2], p2);
                    mma_fp16(a4, Areg[3], p3);
                }
            }

            // epilogue for d-tiles jj = dh*4 + jjl
            #pragma unroll
            for (int jjl = 0; jjl < 4; jjl++){
                int jj = dh*4 + jjl;
                int n0 = 8*jj + 2*tq;
                float2 aI = *(const float2*)(sCa +       n0);
                float2 aF = *(const float2*)(sCa +  64 + n0);
                float2 aG = *(const float2*)(sCa + 128 + n0);
                float2 aO = *(const float2*)(sCa + 192 + n0);
                float2 cI = *(const float2*)(sCb +       n0);
                float2 cF = *(const float2*)(sCb +  64 + n0);
                float2 cG = *(const float2*)(sCb + 128 + n0);
                float2 cO = *(const float2*)(sCb + 192 + n0);
                #pragma unroll
                for (int s = 0; s < 2; s++){
                    float h2[2];
                    #pragma unroll
                    for (int u = 0; u < 2; u++){
                        int fi = s*2 + u;
                        float gi = acc[(     jjl)*4 + fi] + fmaf(u?aI.y:aI.x, xv[s], u?cI.y:cI.x);
                        float gf = acc[( 4 + jjl)*4 + fi] + fmaf(u?aF.y:aF.x, xv[s], u?cF.y:cF.x);
                        float gg = acc[( 8 + jjl)*4 + fi] + fmaf(u?aG.y:aG.x, xv[s], u?cG.y:cG.x);
                        float go = acc[(12 + jjl)*4 + fi] + fmaf(u?aO.y:aO.x, xv[s], u?cO.y:cO.x);
                        int ci = jj*4 + s*2 + u;
                        float c2 = siga(gf)*creg[ci] + siga(gi)*tanha(gg);
                        creg[ci] = c2;
                        h2[u] = siga(go)*tanha(c2);
                    }
                    __half q0 = __float2half_rn(h2[0]);
                    __half q1 = __float2half_rn(h2[1]);
                    u32 hp = (u32)__half_as_ushort(q0) | ((u32)__half_as_ushort(q1) << 16);
                    int K = jj >> 1, hi = jj & 1;
                    if (dh == 0) Anext[K][hi*2 + s] = hp;
                    else         Areg[K][hi*2 + s] = hp;
                }
            }
        }
        #pragma unroll
        for (int K = 0; K < 2; K++)
            #pragma unroll
            for (int q = 0; q < 4; q++) Areg[K][q] = Anext[K][q];
    }

    // ---- final stage (x region is dead only after ALL warps pass here) ----
    __syncthreads();
    float* sHfin = (float*)(sm + SM_X);            // [row][d] stride 64 (16KB)
    float* sCst  = (float*)(sm + SM_X + 16384);    // (16KB)
    #pragma unroll
    for (int K = 0; K < 4; K++){
        #pragma unroll
        for (int hi = 0; hi < 2; hi++){
            #pragma unroll
            for (int s = 0; s < 2; s++){
                u32 v = Areg[K][hi*2 + s];
                int r = wrow + g + 8*s;
                int d0 = 16*K + 8*hi + 2*tq;
                sHfin[r*64 + d0    ] = __half2float(__ushort_as_half((unsigned short)(v & 0xffff)));
                sHfin[r*64 + d0 + 1] = __half2float(__ushort_as_half((unsigned short)(v >> 16)));
                int jj = 2*K + hi;
                sCst[r*64 + d0    ] = creg[jj*4 + s*2 + 0];
                sCst[r*64 + d0 + 1] = creg[jj*4 + s*2 + 1];
            }
        }
    }
    __syncthreads();
    float* sWa = (float*)(sm + SM_B);
    float* sWf = sWa + 4096;
    for (int i = tid; i < 4096; i += NTHR){ sWa[i] = W_aout[i]; sWf[i] = W_fh[i]; }
    __syncthreads();

    const int row = tid >> 1;
    const int db  = (tid & 1) * 32;
    float hh[32];
    #pragma unroll 4
    for (int dd = 0; dd < 32; dd++){
        int d = db + dd;
        float acc2 = __ldg(b_aout + d);
        const float* hr  = sHfin + row*64;
        const float* wr2 = sWa + d*64;
        #pragma unroll
        for (int e = 0; e < 64; e += 4){
            float4 hv = *(const float4*)(hr + e);
            float4 wv = *(const float4*)(wr2 + e);
            acc2 += hv.x*wv.x + hv.y*wv.y + hv.z*wv.z + hv.w*wv.w;
        }
        hh[dd] = acc2;
        atomicAdd(&sRd[64 + d], acc2);
    }
    __syncthreads();
    #pragma unroll 4
    for (int dd = 0; dd < 32; dd++) sHfin[row*64 + db + dd] = hh[dd];
    __syncthreads();
    #pragma unroll 4
    for (int dd = 0; dd < 32; dd++){
        int d = db + dd;
        float f = __ldg(b_fh + d);
        const float* hr  = sHfin + row*64;
        const float* wr2 = sWf + d*64;
        #pragma unroll
        for (int e = 0; e < 64; e += 4){
            float4 hv = *(const float4*)(hr + e);
            float4 wv = *(const float4*)(wr2 + e);
            f += hv.x*wv.x + hv.y*wv.y + hv.z*wv.z + hv.w*wv.w;
        }
        atomicAdd(&sRd[d], sigf(f) * sCst[row*64 + d]);
    }
    __syncthreads();

    // ---- global reduction + last-CTA finisher ----
    atomicAdd(&g_acc[tid], sRd[tid]);
    __threadfence();
    __syncthreads();
    if (tid == 0){
        unsigned int rnk = atomicAdd(&g_ctr, 1);
        *(u32*)(sm + SM_FLG) = (rnk == NBLK - 1) ? 1u : 0u;
    }
    __syncthreads();
    if (*(const u32*)(sm + SM_FLG)){
        float* sfc = (float*)(sm + SM_FIN);
        float* shs = sfc + 64;
        float* sho = sfc + 128;
        if (tid < 64){ sfc[tid] = g_acc[tid]; shs[tid] = g_acc[64 + tid]; }
        __syncthreads();
        if (tid < 64){
            int d = tid;
            float vi = __ldg(b_iouh + d), vo = __ldg(b_iouh + 64 + d), vu = __ldg(b_iouh + 128 + d);
            #pragma unroll 8
            for (int e = 0; e < DD; e++){
                float h = shs[e];
                vi += h * __ldg(W_iouh + (      d)*64 + e);
                vo += h * __ldg(W_iouh + ( 64 + d)*64 + e);
                vu += h * __ldg(W_iouh + (128 + d)*64 + e);
            }
            float cobj = sigf(vi)*tanhp(vu) + sfc[d];
            sho[d] = sigf(vo)*tanhp(cobj);
            out[64 + d] = cobj;
        }
        __syncthreads();
        if (tid < 64){
            int d = tid;
            float acc3 = __ldg(b_oout + d);
            #pragma unroll 8
            for (int e = 0; e < DD; e++) acc3 += sho[e] * __ldg(W_oout + d*64 + e);
            out[d] = acc3;
        }
        g_acc[tid] = 0.f;
        __threadfence();
        if (tid == 0) g_ctr = 0;
    }
}

extern "C" void kernel_launch(void* const* d_in, const int* in_sizes, int n_in,
                              void* d_out, int out_size){
    const float* x      = (const float*)d_in[0];
    const float* W_num  = (const float*)d_in[1];
    const float* b_num  = (const float*)d_in[2];
    const float* W_ih   = (const float*)d_in[3];
    const float* W_hh   = (const float*)d_in[4];
    const float* b_ih   = (const float*)d_in[5];
    const float* b_hh   = (const float*)d_in[6];
    const float* W_aout = (const float*)d_in[7];
    const float* b_aout = (const float*)d_in[8];
    const float* W_fh   = (const float*)d_in[9];
    const float* b_fh   = (const float*)d_in[10];
    const float* W_iouh = (const float*)d_in[11];
    const float* b_iouh = (const float*)d_in[12];
    const float* W_oout = (const float*)d_in[13];
    const float* b_oout = (const float*)d_in[14];
    float* out = (float*)d_out;

    cudaFuncSetAttribute(lstm_kernel, cudaFuncAttributeMaxDynamicSharedMemorySize, SM_TOT);

    lstm_kernel<<<NBLK, NTHR, SM_TOT>>>(x, W_num, b_num, W_ih, W_hh, b_ih, b_hh,
                                        W_aout, b_aout, W_fh, b_fh,
                                        W_iouh, b_iouh, W_oout, b_oout, out);
}